// round 8
// baseline (speedup 1.0000x reference)
#include <cuda_runtime.h>
#include <cuda_fp16.h>

#define B_SZ   16
#define NUM_CN 25000
#define NUM_VN 50000
#define NUM_E  200000
#define D_EMB  16
#define D_HID  32
#define D_MSG  16

typedef unsigned long long ULL;

// ---- scratch (device globals) ----
__device__ __half g_hf_x[(size_t)NUM_CN * B_SZ * D_HID];   // [CN][B][32] fp16
__device__ __half g_hf_z[(size_t)NUM_CN * B_SZ * D_HID];
__device__ __half g_m[(size_t)2 * B_SZ * NUM_VN * D_MSG];  // [pol][b][VN][16] fp16
__device__ int      g_cnt[4 * NUM_VN];                     // deg_x|deg_z|cur_x|cur_z
__device__ int      g_offs_x[NUM_VN + 1], g_offs_z[NUM_VN + 1];
__device__ unsigned g_csr_x[NUM_E],   g_csr_z[NUM_E];      // f | (mask<<16)
__device__ unsigned g_mask_x[NUM_CN], g_mask_z[NUM_CN];

// ---------------------------------------------------------------------------
// f32x2 packed helpers
__device__ __forceinline__ ULL pk2(float x) {
    ULL d; asm("mov.b64 %0, {%1, %1};" : "=l"(d) : "f"(x)); return d;
}
__device__ __forceinline__ ULL pkp(float x, float y) {
    ULL d; asm("mov.b64 %0, {%1, %2};" : "=l"(d) : "f"(x), "f"(y)); return d;
}
__device__ __forceinline__ float2 up2(ULL a) {
    float lo, hi; asm("mov.b64 {%0, %1}, %2;" : "=f"(lo), "=f"(hi) : "l"(a));
    return make_float2(lo, hi);
}
__device__ __forceinline__ ULL f2fma(ULL a, ULL b, ULL c) {
    ULL d; asm("fma.rn.f32x2 %0, %1, %2, %3;" : "=l"(d) : "l"(a), "l"(b), "l"(c));
    return d;
}
__device__ __forceinline__ float4 mk4(ULL a, ULL b) {
    float2 p = up2(a), q = up2(b);
    return make_float4(p.x, p.y, q.x, q.y);
}

// ---------------------------------------------------------------------------
// kernel 1: degree histogram + syndrome bitmask pack
__global__ void __launch_bounds__(256) prep_kernel(
    const int* __restrict__ to_x, const int* __restrict__ to_z,
    const int* __restrict__ syn_x, const int* __restrict__ syn_z,
    int* __restrict__ deg_x, int* __restrict__ deg_z,
    unsigned* __restrict__ mask_x, unsigned* __restrict__ mask_z)
{
    int i = blockIdx.x * 256 + threadIdx.x;
    if (i < NUM_E) {
        atomicAdd(&deg_x[__ldg(to_x + i)], 1);
        atomicAdd(&deg_z[__ldg(to_z + i)], 1);
    }
    if (i < NUM_CN) {
        unsigned mx = 0, mz = 0;
        #pragma unroll
        for (int b = 0; b < B_SZ; b++) {
            mx |= (unsigned)(__ldg(syn_x + (size_t)b * NUM_CN + i) & 1) << b;
            mz |= (unsigned)(__ldg(syn_z + (size_t)b * NUM_CN + i) & 1) << b;
        }
        mask_x[i] = mx;
        mask_z[i] = mz;
    }
}

// ---------------------------------------------------------------------------
// kernel 2: exclusive scan, one block per polarity (1024 threads, warp scans)
__global__ void __launch_bounds__(1024) scan_kernel(
    const int* __restrict__ deg_x, const int* __restrict__ deg_z,
    int* __restrict__ offs_x, int* __restrict__ offs_z)
{
    const int* deg  = blockIdx.x == 0 ? deg_x  : deg_z;
    int*       offs = blockIdx.x == 0 ? offs_x : offs_z;

    __shared__ int wt[32];
    __shared__ int sbase;
    int t = threadIdx.x;
    int lane = t & 31, w = t >> 5;
    if (t == 0) sbase = 0;
    __syncthreads();

    for (int c = 0; c < NUM_VN; c += 1024) {
        int gid = c + t;
        int x = (gid < NUM_VN) ? deg[gid] : 0;
        #pragma unroll
        for (int o = 1; o < 32; o <<= 1) {
            int y = __shfl_up_sync(0xffffffffu, x, o);
            if (lane >= o) x += y;
        }
        if (lane == 31) wt[w] = x;
        __syncthreads();
        if (w == 0) {
            int y = wt[lane];
            #pragma unroll
            for (int o = 1; o < 32; o <<= 1) {
                int z = __shfl_up_sync(0xffffffffu, y, o);
                if (lane >= o) y += z;
            }
            wt[lane] = y;
        }
        __syncthreads();
        int incl = x + (w > 0 ? wt[w - 1] : 0) + sbase;
        if (gid < NUM_VN) offs[gid + 1] = incl;
        __syncthreads();
        if (t == 1023) sbase = incl;
        __syncthreads();
    }
    if (t == 0) offs[0] = 0;
}

// ---------------------------------------------------------------------------
// kernel 3: fused CSR fill (y=2) + node partials (y=0,1)
__global__ void __launch_bounds__(256) fill_np_kernel(
    const int* __restrict__ from_x, const int* __restrict__ to_x,
    const int* __restrict__ from_z, const int* __restrict__ to_z,
    const int* __restrict__ offs_x, const int* __restrict__ offs_z,
    const unsigned* __restrict__ mask_x, const unsigned* __restrict__ mask_z,
    int* __restrict__ cur_x, int* __restrict__ cur_z,
    unsigned* __restrict__ csr_x, unsigned* __restrict__ csr_z,
    const float* __restrict__ hx, const float* __restrict__ hz,
    const float* __restrict__ Wx1, const float* __restrict__ Wz1,
    __half* __restrict__ ox, __half* __restrict__ oz)
{
    if (blockIdx.y == 2) {
        int e = blockIdx.x * 256 + threadIdx.x;
        if (e >= NUM_E) return;
        {
            int v = __ldg(to_x + e);
            int f = __ldg(from_x + e);
            int p = atomicAdd(&cur_x[v], 1);
            csr_x[__ldg(offs_x + v) + p] = (unsigned)f | (__ldg(mask_x + f) << 16);
        }
        {
            int v = __ldg(to_z + e);
            int f = __ldg(from_z + e);
            int p = atomicAdd(&cur_z[v], 1);
            csr_z[__ldg(offs_z + v) + p] = (unsigned)f | (__ldg(mask_z + f) << 16);
        }
        return;
    }

    const float* h  = blockIdx.y == 0 ? hx  : hz;
    const float* W1 = blockIdx.y == 0 ? Wx1 : Wz1;
    __half*      o  = blockIdx.y == 0 ? ox  : oz;

    __shared__ float4 sW1[128];   // W1 rows 0..15 (16x32)
    int t = threadIdx.x;
    if (t < 128) sW1[t] = reinterpret_cast<const float4*>(W1)[t];
    __syncthreads();

    int wid = t >> 5;
    int unit = blockIdx.x * 8 + wid;          // n*4 + bgroup, < 100000
    if (unit >= NUM_CN * 4) return;
    int n = unit >> 2;
    int b = ((unit & 3) << 2) | ((t >> 3) & 3);
    int chunk = t & 7;

    const float4* ph = reinterpret_cast<const float4*>(h + ((size_t)b * NUM_CN + n) * D_EMB);
    float4 h0 = ph[0], h1 = ph[1], h2 = ph[2], h3 = ph[3];
    float hr[16] = {h0.x,h0.y,h0.z,h0.w, h1.x,h1.y,h1.z,h1.w,
                    h2.x,h2.y,h2.z,h2.w, h3.x,h3.y,h3.z,h3.w};

    ULL a0 = 0ull, a1 = 0ull;
    #pragma unroll
    for (int d = 0; d < 16; d++) {
        float4 w = sW1[d*8 + chunk];
        ULL hd = pk2(hr[d]);
        a0 = f2fma(hd, pkp(w.x, w.y), a0);
        a1 = f2fma(hd, pkp(w.z, w.w), a1);
    }

    __half2 lo = __float22half2_rn(up2(a0));
    __half2 hi = __float22half2_rn(up2(a1));
    uint2 st;
    st.x = *reinterpret_cast<unsigned*>(&lo);
    st.y = *reinterpret_cast<unsigned*>(&hi);
    reinterpret_cast<uint2*>(o)[((size_t)n * B_SZ + b) * 8 + chunk] = st;
}

// ---------------------------------------------------------------------------
// kernel 4 (PROFILED SLOT): msg kernel.
// grid.y = polarity; warp = one v x 4 consecutive b; lane = b_local*8+chunk.
// Lane-parallel CSR gather: csr[beg+lane] loaded once, shfl-broadcast per edge.
__global__ void __launch_bounds__(256) msg_kernel(
    const float* __restrict__ h_to,
    const __half* __restrict__ hfx, const __half* __restrict__ hfz,
    const int* __restrict__ offs_x, const unsigned* __restrict__ csr_x,
    const int* __restrict__ offs_z, const unsigned* __restrict__ csr_z,
    const float* __restrict__ Wx1, const float* __restrict__ Wz1,
    const float* __restrict__ Wx2, const float* __restrict__ Wz2,
    __half* __restrict__ m)
{
    int pol = blockIdx.y;
    const uint2*    hf2  = reinterpret_cast<const uint2*>(pol ? hfz : hfx);
    const int*      offs = pol ? offs_z : offs_x;
    const unsigned* csr  = pol ? csr_z  : csr_x;

    __shared__ float4 sW1[128];   // W1 rows 16..31 (16x32)
    __shared__ float  sW2[512];   // W2 (32x16)
    {
        const float4* w1 = reinterpret_cast<const float4*>((pol ? Wz1 : Wx1) + 16 * 32);
        const float4* w2 = reinterpret_cast<const float4*>(pol ? Wz2 : Wx2);
        int t = threadIdx.x;
        if (t < 128) {
            sW1[t] = w1[t];
            reinterpret_cast<float4*>(sW2)[t] = w2[t];
        }
    }
    __syncthreads();

    int t = threadIdx.x;
    int wid = t >> 5;
    int lane = t & 31;
    int unit = blockIdx.x * 8 + wid;          // v*4 + bgroup, < 200000
    int v = unit >> 2;
    int b = ((unit & 3) << 2) | ((t >> 3) & 3);
    int chunk = t & 7;

    // hp: lane's 4 hidden dims of h_to partial
    ULL hp0 = 0ull, hp1 = 0ull;
    {
        const float4* ph = reinterpret_cast<const float4*>(
            h_to + ((size_t)b * NUM_VN + v) * D_EMB);
        float4 h0 = ph[0], h1 = ph[1], h2 = ph[2], h3 = ph[3];
        float hr[16] = {h0.x,h0.y,h0.z,h0.w, h1.x,h1.y,h1.z,h1.w,
                        h2.x,h2.y,h2.z,h2.w, h3.x,h3.y,h3.z,h3.w};
        #pragma unroll
        for (int d = 0; d < 16; d++) {
            float4 w = sW1[d*8 + chunk];
            ULL hd = pk2(hr[d]);
            hp0 = f2fma(hd, pkp(w.x, w.y), hp0);
            hp1 = f2fma(hd, pkp(w.z, w.w), hp1);
        }
    }
    float2 hpa = up2(hp0), hpb = up2(hp1);

    // lane-parallel CSR gather + shfl-broadcast edge walk
    float s0 = 0.f, s1 = 0.f, s2 = 0.f, s3 = 0.f;
    int beg = __ldg(offs + v), end = __ldg(offs + v + 1);
    int deg = end - beg;                       // uniform across warp
    unsigned shift = 16 + b;
    unsigned myk = (lane < deg) ? __ldg(csr + beg + lane) : 0u;

    int n32 = min(deg, 32);
    for (int i = 0; i < n32; i++) {
        unsigned pk = __shfl_sync(0xffffffffu, myk, i);
        if ((pk >> shift) & 1u) {
            uint2 hv = hf2[((size_t)(pk & 0xFFFFu) * B_SZ + b) * 8 + chunk];
            float2 lo = __half22float2(*reinterpret_cast<__half2*>(&hv.x));
            float2 hi = __half22float2(*reinterpret_cast<__half2*>(&hv.y));
            s0 += fmaxf(lo.x + hpa.x, 0.f);
            s1 += fmaxf(lo.y + hpa.y, 0.f);
            s2 += fmaxf(hi.x + hpb.x, 0.f);
            s3 += fmaxf(hi.y + hpb.y, 0.f);
        }
    }
    // rare tail (deg > 32)
    for (int e = beg + 32; e < end; e++) {
        unsigned pk = __ldg(csr + e);
        if ((pk >> shift) & 1u) {
            uint2 hv = hf2[((size_t)(pk & 0xFFFFu) * B_SZ + b) * 8 + chunk];
            float2 lo = __half22float2(*reinterpret_cast<__half2*>(&hv.x));
            float2 hi = __half22float2(*reinterpret_cast<__half2*>(&hv.y));
            s0 += fmaxf(lo.x + hpa.x, 0.f);
            s1 += fmaxf(lo.y + hpa.y, 0.f);
            s2 += fmaxf(hi.x + hpb.x, 0.f);
            s3 += fmaxf(hi.y + hpb.y, 0.f);
        }
    }

    // msg = s @ W2 : lane computes msg dims 2*chunk, 2*chunk+1
    const ULL* sW2p = reinterpret_cast<const ULL*>(sW2);
    ULL acc = 0ull;
    float sv[4] = {s0, s1, s2, s3};
    #pragma unroll
    for (int j = 0; j < 32; j++) {
        float sj = __shfl_sync(0xffffffffu, sv[j & 3], j >> 2, 8);
        acc = f2fma(pk2(sj), sW2p[j*8 + chunk], acc);
    }

    // store fp16 msg pair, layout [pol][b][VN][16]
    __half2 hm = __float22half2_rn(up2(acc));
    reinterpret_cast<unsigned*>(m)[
        (((size_t)pol * B_SZ + b) * NUM_VN + v) * 8 + chunk] =
        *reinterpret_cast<unsigned*>(&hm);
}

// ---------------------------------------------------------------------------
// kernel 5: vn kernel, b-major flat mapping -> all accesses idx-linear
__global__ void __launch_bounds__(256, 2) vn_kernel(
    const __half* __restrict__ m, const float* __restrict__ h_to,
    const float* __restrict__ We1, const float* __restrict__ We2,
    float* __restrict__ out)
{
    __shared__ float4 sW1[384];   // We1 48x32
    __shared__ float4 sW2[128];   // We2 32x16
    int t = threadIdx.x;
    for (int i = t; i < 384; i += 256) sW1[i] = reinterpret_cast<const float4*>(We1)[i];
    if (t < 128) sW2[t] = reinterpret_cast<const float4*>(We2)[t];
    __syncthreads();

    int idx = blockIdx.x * 256 + t;   // idx = b*NUM_VN + v  (800000 = 3125*256)
    const size_t BVN = (size_t)B_SZ * NUM_VN;

    float feat[48];
    {
        const uint4* mb = reinterpret_cast<const uint4*>(m);
        const uint4* px = mb + (size_t)idx * 2;          // pol 0
        const uint4* pz = mb + (BVN + idx) * 2;          // pol 1
        #pragma unroll
        for (int q = 0; q < 2; q++) {
            uint4 a = px[q];
            unsigned w[4] = {a.x, a.y, a.z, a.w};
            #pragma unroll
            for (int k = 0; k < 4; k++) {
                float2 p = __half22float2(*reinterpret_cast<__half2*>(&w[k]));
                feat[q*8 + 2*k + 0] = p.x;
                feat[q*8 + 2*k + 1] = p.y;
            }
        }
        #pragma unroll
        for (int q = 0; q < 2; q++) {
            uint4 a = pz[q];
            unsigned w[4] = {a.x, a.y, a.z, a.w};
            #pragma unroll
            for (int k = 0; k < 4; k++) {
                float2 p = __half22float2(*reinterpret_cast<__half2*>(&w[k]));
                feat[16 + q*8 + 2*k + 0] = p.x;
                feat[16 + q*8 + 2*k + 1] = p.y;
            }
        }
        const float4* ph = reinterpret_cast<const float4*>(h_to + (size_t)idx * D_EMB);
        #pragma unroll
        for (int q = 0; q < 4; q++) {
            float4 a = ph[q];
            feat[32+4*q+0]=a.x; feat[32+4*q+1]=a.y; feat[32+4*q+2]=a.z; feat[32+4*q+3]=a.w;
        }
    }

    ULL acc[16];
    #pragma unroll
    for (int q = 0; q < 16; q++) acc[q] = 0ull;
    #pragma unroll
    for (int d = 0; d < 48; d++) {
        ULL fd = pk2(feat[d]);
        #pragma unroll
        for (int k = 0; k < 8; k++) {
            float4 w = sW1[d*8 + k];
            acc[2*k+0] = f2fma(fd, pkp(w.x, w.y), acc[2*k+0]);
            acc[2*k+1] = f2fma(fd, pkp(w.z, w.w), acc[2*k+1]);
        }
    }

    float hid[32];
    #pragma unroll
    for (int q = 0; q < 16; q++) {
        float2 p = up2(acc[q]);
        hid[2*q+0] = fmaxf(p.x, 0.f);
        hid[2*q+1] = fmaxf(p.y, 0.f);
    }

    ULL o[8];
    #pragma unroll
    for (int q = 0; q < 8; q++) o[q] = 0ull;
    #pragma unroll
    for (int j = 0; j < 32; j++) {
        ULL hj = pk2(hid[j]);
        #pragma unroll
        for (int k = 0; k < 4; k++) {
            float4 w = sW2[j*4 + k];
            o[2*k+0] = f2fma(hj, pkp(w.x, w.y), o[2*k+0]);
            o[2*k+1] = f2fma(hj, pkp(w.z, w.w), o[2*k+1]);
        }
    }

    float4* op = reinterpret_cast<float4*>(out + (size_t)idx * D_EMB);
    #pragma unroll
    for (int q = 0; q < 4; q++) op[q] = mk4(o[2*q], o[2*q+1]);
}

// ---------------------------------------------------------------------------
extern "C" void kernel_launch(void* const* d_in, const int* in_sizes, int n_in,
                              void* d_out, int out_size) {
    const float* h_from_x   = (const float*)d_in[0];
    const float* h_from_z   = (const float*)d_in[1];
    const float* h_to       = (const float*)d_in[2];
    const int*   syndrome_x = (const int*)d_in[3];
    const int*   syndrome_z = (const int*)d_in[4];
    const int*   from_ind_x = (const int*)d_in[5];
    const int*   to_ind_x   = (const int*)d_in[6];
    const int*   from_ind_z = (const int*)d_in[7];
    const int*   to_ind_z   = (const int*)d_in[8];
    const float* Wx1        = (const float*)d_in[9];
    const float* Wx2        = (const float*)d_in[10];
    const float* Wz1        = (const float*)d_in[11];
    const float* Wz2        = (const float*)d_in[12];
    const float* We1        = (const float*)d_in[13];
    const float* We2        = (const float*)d_in[14];
    float* out = (float*)d_out;

    __half *hf_x, *hf_z, *m;
    int *cnt, *offs_x, *offs_z;
    unsigned *csr_x, *csr_z, *mask_x, *mask_z;
    cudaGetSymbolAddress((void**)&hf_x, g_hf_x);
    cudaGetSymbolAddress((void**)&hf_z, g_hf_z);
    cudaGetSymbolAddress((void**)&m,    g_m);
    cudaGetSymbolAddress((void**)&cnt,  g_cnt);
    cudaGetSymbolAddress((void**)&offs_x, g_offs_x);
    cudaGetSymbolAddress((void**)&offs_z, g_offs_z);
    cudaGetSymbolAddress((void**)&csr_x, g_csr_x);
    cudaGetSymbolAddress((void**)&csr_z, g_csr_z);
    cudaGetSymbolAddress((void**)&mask_x, g_mask_x);
    cudaGetSymbolAddress((void**)&mask_z, g_mask_z);

    int *deg_x = cnt, *deg_z = cnt + NUM_VN;
    int *cur_x = cnt + 2 * NUM_VN, *cur_z = cnt + 3 * NUM_VN;

    cudaMemsetAsync(cnt, 0, 4 * NUM_VN * sizeof(int), 0);

    // k1: histogram + masks
    prep_kernel<<<(NUM_E + 255) / 256, 256>>>(
        to_ind_x, to_ind_z, syndrome_x, syndrome_z,
        deg_x, deg_z, mask_x, mask_z);

    // k2: scan (one block per polarity)
    scan_kernel<<<2, 1024>>>(deg_x, deg_z, offs_x, offs_z);

    // k3: fused CSR fill (y=2) + node partials (y=0,1)
    fill_np_kernel<<<dim3(12500, 3), 256>>>(
        from_ind_x, to_ind_x, from_ind_z, to_ind_z,
        offs_x, offs_z, mask_x, mask_z, cur_x, cur_z, csr_x, csr_z,
        h_from_x, h_from_z, Wx1, Wz1, hf_x, hf_z);

    // k4 (profiled slot): messages
    msg_kernel<<<dim3(25000, 2), 256>>>(
        h_to, hf_x, hf_z,
        offs_x, csr_x, offs_z, csr_z,
        Wx1, Wz1, Wx2, Wz2, m);

    // k5: vertex MLP
    vn_kernel<<<(NUM_VN * B_SZ) / 256, 256>>>(m, h_to, We1, We2, out);
}

// round 9
// speedup vs baseline: 1.1283x; 1.1283x over previous
#include <cuda_runtime.h>
#include <cuda_fp16.h>

#define B_SZ   16
#define NUM_CN 25000
#define NUM_VN 50000
#define NUM_E  200000
#define D_EMB  16
#define D_HID  32
#define D_MSG  16

typedef unsigned long long ULL;

// ---- scratch (device globals) ----
__device__ __half g_hf_x[(size_t)NUM_CN * B_SZ * D_HID];   // [CN][B][32] fp16
__device__ __half g_hf_z[(size_t)NUM_CN * B_SZ * D_HID];
__device__ __half g_s[(size_t)2 * B_SZ * NUM_VN * D_HID];  // [pol][b][VN][32] fp16
__device__ float  g_M[2 * 32 * 32];                        // Mx | Mz combined mats
__device__ int      g_cnt[4 * NUM_VN];                     // deg_x|deg_z|cur_x|cur_z
__device__ int      g_offs_x[NUM_VN + 1], g_offs_z[NUM_VN + 1];
__device__ unsigned g_csr_x[NUM_E],   g_csr_z[NUM_E];      // f | (mask<<16)
__device__ unsigned g_mask_x[NUM_CN], g_mask_z[NUM_CN];

// ---------------------------------------------------------------------------
// f32x2 packed helpers
__device__ __forceinline__ ULL pk2(float x) {
    ULL d; asm("mov.b64 %0, {%1, %1};" : "=l"(d) : "f"(x)); return d;
}
__device__ __forceinline__ ULL pkp(float x, float y) {
    ULL d; asm("mov.b64 %0, {%1, %2};" : "=l"(d) : "f"(x), "f"(y)); return d;
}
__device__ __forceinline__ float2 up2(ULL a) {
    float lo, hi; asm("mov.b64 {%0, %1}, %2;" : "=f"(lo), "=f"(hi) : "l"(a));
    return make_float2(lo, hi);
}
__device__ __forceinline__ ULL f2fma(ULL a, ULL b, ULL c) {
    ULL d; asm("fma.rn.f32x2 %0, %1, %2, %3;" : "=l"(d) : "l"(a), "l"(b), "l"(c));
    return d;
}
__device__ __forceinline__ float4 mk4(ULL a, ULL b) {
    float2 p = up2(a), q = up2(b);
    return make_float4(p.x, p.y, q.x, q.y);
}

// ---------------------------------------------------------------------------
// kernel 1: degree histogram + syndrome bitmask pack
__global__ void __launch_bounds__(256) prep_kernel(
    const int* __restrict__ to_x, const int* __restrict__ to_z,
    const int* __restrict__ syn_x, const int* __restrict__ syn_z,
    int* __restrict__ deg_x, int* __restrict__ deg_z,
    unsigned* __restrict__ mask_x, unsigned* __restrict__ mask_z)
{
    int i = blockIdx.x * 256 + threadIdx.x;
    if (i < NUM_E) {
        atomicAdd(&deg_x[__ldg(to_x + i)], 1);
        atomicAdd(&deg_z[__ldg(to_z + i)], 1);
    }
    if (i < NUM_CN) {
        unsigned mx = 0, mz = 0;
        #pragma unroll
        for (int b = 0; b < B_SZ; b++) {
            mx |= (unsigned)(__ldg(syn_x + (size_t)b * NUM_CN + i) & 1) << b;
            mz |= (unsigned)(__ldg(syn_z + (size_t)b * NUM_CN + i) & 1) << b;
        }
        mask_x[i] = mx;
        mask_z[i] = mz;
    }
}

// ---------------------------------------------------------------------------
// kernel 2: exclusive scan (blocks 0,1) + combined-matrix precompute (block 2)
// Mx = Wx2 @ We1[0:16]  (32x16 @ 16x32),  Mz = Wz2 @ We1[16:32]
__global__ void __launch_bounds__(1024) scan_kernel(
    const int* __restrict__ deg_x, const int* __restrict__ deg_z,
    int* __restrict__ offs_x, int* __restrict__ offs_z,
    const float* __restrict__ Wx2, const float* __restrict__ Wz2,
    const float* __restrict__ We1, float* __restrict__ M)
{
    if (blockIdx.x == 2) {
        int t = threadIdx.x;
        #pragma unroll
        for (int r = 0; r < 2; r++) {
            int el = r * 1024 + t;            // 0..2047
            int pol = el >> 10;               // 0: Mx, 1: Mz
            int i = (el >> 5) & 31;           // row (s dim)
            int j = el & 31;                  // col (hid dim)
            const float* W2 = pol ? Wz2 : Wx2;
            const float* E1 = We1 + pol * 16 * 32;
            float sum = 0.f;
            #pragma unroll
            for (int k = 0; k < 16; k++)
                sum += W2[i * 16 + k] * E1[k * 32 + j];
            M[el] = sum;
        }
        return;
    }

    const int* deg  = blockIdx.x == 0 ? deg_x  : deg_z;
    int*       offs = blockIdx.x == 0 ? offs_x : offs_z;

    __shared__ int wt[32];
    __shared__ int sbase;
    int t = threadIdx.x;
    int lane = t & 31, w = t >> 5;
    if (t == 0) sbase = 0;
    __syncthreads();

    for (int c = 0; c < NUM_VN; c += 1024) {
        int gid = c + t;
        int x = (gid < NUM_VN) ? deg[gid] : 0;
        #pragma unroll
        for (int o = 1; o < 32; o <<= 1) {
            int y = __shfl_up_sync(0xffffffffu, x, o);
            if (lane >= o) x += y;
        }
        if (lane == 31) wt[w] = x;
        __syncthreads();
        if (w == 0) {
            int y = wt[lane];
            #pragma unroll
            for (int o = 1; o < 32; o <<= 1) {
                int z = __shfl_up_sync(0xffffffffu, y, o);
                if (lane >= o) y += z;
            }
            wt[lane] = y;
        }
        __syncthreads();
        int incl = x + (w > 0 ? wt[w - 1] : 0) + sbase;
        if (gid < NUM_VN) offs[gid + 1] = incl;
        __syncthreads();
        if (t == 1023) sbase = incl;
        __syncthreads();
    }
    if (t == 0) offs[0] = 0;
}

// ---------------------------------------------------------------------------
// kernel 3: fused CSR fill (y=2) + node partials (y=0,1)
__global__ void __launch_bounds__(256) fill_np_kernel(
    const int* __restrict__ from_x, const int* __restrict__ to_x,
    const int* __restrict__ from_z, const int* __restrict__ to_z,
    const int* __restrict__ offs_x, const int* __restrict__ offs_z,
    const unsigned* __restrict__ mask_x, const unsigned* __restrict__ mask_z,
    int* __restrict__ cur_x, int* __restrict__ cur_z,
    unsigned* __restrict__ csr_x, unsigned* __restrict__ csr_z,
    const float* __restrict__ hx, const float* __restrict__ hz,
    const float* __restrict__ Wx1, const float* __restrict__ Wz1,
    __half* __restrict__ ox, __half* __restrict__ oz)
{
    if (blockIdx.y == 2) {
        int e = blockIdx.x * 256 + threadIdx.x;
        if (e >= NUM_E) return;
        {
            int v = __ldg(to_x + e);
            int f = __ldg(from_x + e);
            int p = atomicAdd(&cur_x[v], 1);
            csr_x[__ldg(offs_x + v) + p] = (unsigned)f | (__ldg(mask_x + f) << 16);
        }
        {
            int v = __ldg(to_z + e);
            int f = __ldg(from_z + e);
            int p = atomicAdd(&cur_z[v], 1);
            csr_z[__ldg(offs_z + v) + p] = (unsigned)f | (__ldg(mask_z + f) << 16);
        }
        return;
    }

    const float* h  = blockIdx.y == 0 ? hx  : hz;
    const float* W1 = blockIdx.y == 0 ? Wx1 : Wz1;
    __half*      o  = blockIdx.y == 0 ? ox  : oz;

    __shared__ float4 sW1[128];   // W1 rows 0..15 (16x32)
    int t = threadIdx.x;
    if (t < 128) sW1[t] = reinterpret_cast<const float4*>(W1)[t];
    __syncthreads();

    int wid = t >> 5;
    int unit = blockIdx.x * 8 + wid;          // n*4 + bgroup, < 100000
    if (unit >= NUM_CN * 4) return;
    int n = unit >> 2;
    int b = ((unit & 3) << 2) | ((t >> 3) & 3);
    int chunk = t & 7;

    const float4* ph = reinterpret_cast<const float4*>(h + ((size_t)b * NUM_CN + n) * D_EMB);
    float4 h0 = ph[0], h1 = ph[1], h2 = ph[2], h3 = ph[3];
    float hr[16] = {h0.x,h0.y,h0.z,h0.w, h1.x,h1.y,h1.z,h1.w,
                    h2.x,h2.y,h2.z,h2.w, h3.x,h3.y,h3.z,h3.w};

    ULL a0 = 0ull, a1 = 0ull;
    #pragma unroll
    for (int d = 0; d < 16; d++) {
        float4 w = sW1[d*8 + chunk];
        ULL hd = pk2(hr[d]);
        a0 = f2fma(hd, pkp(w.x, w.y), a0);
        a1 = f2fma(hd, pkp(w.z, w.w), a1);
    }

    __half2 lo = __float22half2_rn(up2(a0));
    __half2 hi = __float22half2_rn(up2(a1));
    uint2 st;
    st.x = *reinterpret_cast<unsigned*>(&lo);
    st.y = *reinterpret_cast<unsigned*>(&hi);
    reinterpret_cast<uint2*>(o)[((size_t)n * B_SZ + b) * 8 + chunk] = st;
}

// ---------------------------------------------------------------------------
// kernel 4 (PROFILED SLOT): msg kernel — gather + relu-sum ONLY (no W2).
// grid.y = polarity; warp = one v, loops over 4 bgroups (all 16 b);
// lane = b_local*8 + chunk owns hidden dims 4*chunk..+4.
__global__ void __launch_bounds__(256) msg_kernel(
    const float* __restrict__ h_to,
    const __half* __restrict__ hfx, const __half* __restrict__ hfz,
    const int* __restrict__ offs_x, const unsigned* __restrict__ csr_x,
    const int* __restrict__ offs_z, const unsigned* __restrict__ csr_z,
    const float* __restrict__ Wx1, const float* __restrict__ Wz1,
    __half* __restrict__ s_out)
{
    int pol = blockIdx.y;
    const uint2*    hf2  = reinterpret_cast<const uint2*>(pol ? hfz : hfx);
    const int*      offs = pol ? offs_z : offs_x;
    const unsigned* csr  = pol ? csr_z  : csr_x;

    __shared__ float4 sW1[128];   // W1 rows 16..31 (16x32)
    {
        const float4* w1 = reinterpret_cast<const float4*>((pol ? Wz1 : Wx1) + 16 * 32);
        int t = threadIdx.x;
        if (t < 128) sW1[t] = w1[t];
    }
    __syncthreads();

    int t = threadIdx.x;
    int wid = t >> 5;
    int lane = t & 31;
    int v = blockIdx.x * 8 + wid;             // grid.x=6250 -> v in [0,50000)
    int b_hi = (lane >> 3) & 3;
    int chunk = lane & 7;

    int beg = __ldg(offs + v), end = __ldg(offs + v + 1);

    #pragma unroll
    for (int bg = 0; bg < 4; bg++) {
        int b = bg * 4 + b_hi;

        // hp = h_to[b][v] @ W1[16:32], lane's 4 hidden dims
        ULL hp0 = 0ull, hp1 = 0ull;
        {
            const float4* ph = reinterpret_cast<const float4*>(
                h_to + ((size_t)b * NUM_VN + v) * D_EMB);
            float4 h0 = ph[0], h1 = ph[1], h2 = ph[2], h3 = ph[3];
            float hr[16] = {h0.x,h0.y,h0.z,h0.w, h1.x,h1.y,h1.z,h1.w,
                            h2.x,h2.y,h2.z,h2.w, h3.x,h3.y,h3.z,h3.w};
            #pragma unroll
            for (int d = 0; d < 16; d++) {
                float4 w = sW1[d*8 + chunk];
                ULL hd = pk2(hr[d]);
                hp0 = f2fma(hd, pkp(w.x, w.y), hp0);
                hp1 = f2fma(hd, pkp(w.z, w.w), hp1);
            }
        }
        float2 hpa = up2(hp0), hpb = up2(hp1);

        // edge walk (uniform broadcast csr loads, 2-wide)
        float s0 = 0.f, s1 = 0.f, s2 = 0.f, s3 = 0.f;
        unsigned shift = 16 + b;
        for (int e = beg; e < end; e += 2) {
            unsigned pa = __ldg(csr + e);
            unsigned pb = (e + 1 < end) ? __ldg(csr + e + 1) : 0u;
            bool ga = (pa >> shift) & 1u;
            bool gb = (pb >> shift) & 1u;
            uint2 va, vb;
            if (ga) va = hf2[((size_t)(pa & 0xFFFFu) * B_SZ + b) * 8 + chunk];
            if (gb) vb = hf2[((size_t)(pb & 0xFFFFu) * B_SZ + b) * 8 + chunk];
            if (ga) {
                float2 lo = __half22float2(*reinterpret_cast<__half2*>(&va.x));
                float2 hi = __half22float2(*reinterpret_cast<__half2*>(&va.y));
                s0 += fmaxf(lo.x + hpa.x, 0.f);
                s1 += fmaxf(lo.y + hpa.y, 0.f);
                s2 += fmaxf(hi.x + hpb.x, 0.f);
                s3 += fmaxf(hi.y + hpb.y, 0.f);
            }
            if (gb) {
                float2 lo = __half22float2(*reinterpret_cast<__half2*>(&vb.x));
                float2 hi = __half22float2(*reinterpret_cast<__half2*>(&vb.y));
                s0 += fmaxf(lo.x + hpa.x, 0.f);
                s1 += fmaxf(lo.y + hpa.y, 0.f);
                s2 += fmaxf(hi.x + hpb.x, 0.f);
                s3 += fmaxf(hi.y + hpb.y, 0.f);
            }
        }

        // store raw s (4 halves), layout [pol][b][VN][32]
        __half2 lo = __float22half2_rn(make_float2(s0, s1));
        __half2 hi = __float22half2_rn(make_float2(s2, s3));
        uint2 st;
        st.x = *reinterpret_cast<unsigned*>(&lo);
        st.y = *reinterpret_cast<unsigned*>(&hi);
        reinterpret_cast<uint2*>(s_out)[
            (((size_t)pol * B_SZ + b) * NUM_VN + v) * 8 + chunk] = st;
    }
}

// ---------------------------------------------------------------------------
// kernel 5: vn kernel — out = relu(sx@Mx + sz@Mz + h_to@We1[32:48]) @ We2
// b-major flat mapping, all accesses idx-linear.
__global__ void __launch_bounds__(256) vn_kernel(
    const __half* __restrict__ s, const float* __restrict__ h_to,
    const float* __restrict__ M, const float* __restrict__ We1,
    const float* __restrict__ We2, float* __restrict__ out)
{
    __shared__ float4 sW1[640];   // 80 rows x 32 cols: Mx(32) | Mz(32) | We1[32:48](16)
    __shared__ float4 sW2[128];   // We2 32x16
    int t = threadIdx.x;
    for (int i = t; i < 512; i += 256) sW1[i] = reinterpret_cast<const float4*>(M)[i];
    if (t < 128) sW1[512 + t] = reinterpret_cast<const float4*>(We1 + 32 * 32)[t];
    if (t < 128) sW2[t] = reinterpret_cast<const float4*>(We2)[t];
    __syncthreads();

    int idx = blockIdx.x * 256 + t;   // idx = b*NUM_VN + v  (800000 = 3125*256)
    const size_t BVN = (size_t)B_SZ * NUM_VN;

    // load sx, sz as packed half2 (16 regs each)
    unsigned ux[16], uz[16];
    {
        const uint4* px = reinterpret_cast<const uint4*>(s) + (size_t)idx * 4;
        const uint4* pz = reinterpret_cast<const uint4*>(s) + (BVN + idx) * 4;
        #pragma unroll
        for (int q = 0; q < 4; q++) {
            uint4 a = px[q];
            ux[4*q+0]=a.x; ux[4*q+1]=a.y; ux[4*q+2]=a.z; ux[4*q+3]=a.w;
        }
        #pragma unroll
        for (int q = 0; q < 4; q++) {
            uint4 a = pz[q];
            uz[4*q+0]=a.x; uz[4*q+1]=a.y; uz[4*q+2]=a.z; uz[4*q+3]=a.w;
        }
    }
    float ft[16];
    {
        const float4* ph = reinterpret_cast<const float4*>(h_to + (size_t)idx * D_EMB);
        #pragma unroll
        for (int q = 0; q < 4; q++) {
            float4 a = ph[q];
            ft[4*q+0]=a.x; ft[4*q+1]=a.y; ft[4*q+2]=a.z; ft[4*q+3]=a.w;
        }
    }

    ULL acc[16];
    #pragma unroll
    for (int q = 0; q < 16; q++) acc[q] = 0ull;

    // rows 0..31: sx @ Mx
    #pragma unroll
    for (int dp = 0; dp < 16; dp++) {
        float2 p = __half22float2(*reinterpret_cast<__half2*>(&ux[dp]));
        ULL f0 = pk2(p.x), f1 = pk2(p.y);
        const float4* r0 = &sW1[(2*dp) * 8];
        #pragma unroll
        for (int k = 0; k < 8; k++) {
            float4 w = r0[k];
            acc[2*k+0] = f2fma(f0, pkp(w.x, w.y), acc[2*k+0]);
            acc[2*k+1] = f2fma(f0, pkp(w.z, w.w), acc[2*k+1]);
        }
        const float4* r1 = &sW1[(2*dp+1) * 8];
        #pragma unroll
        for (int k = 0; k < 8; k++) {
            float4 w = r1[k];
            acc[2*k+0] = f2fma(f1, pkp(w.x, w.y), acc[2*k+0]);
            acc[2*k+1] = f2fma(f1, pkp(w.z, w.w), acc[2*k+1]);
        }
    }
    // rows 32..63: sz @ Mz
    #pragma unroll
    for (int dp = 0; dp < 16; dp++) {
        float2 p = __half22float2(*reinterpret_cast<__half2*>(&uz[dp]));
        ULL f0 = pk2(p.x), f1 = pk2(p.y);
        const float4* r0 = &sW1[(32 + 2*dp) * 8];
        #pragma unroll
        for (int k = 0; k < 8; k++) {
            float4 w = r0[k];
            acc[2*k+0] = f2fma(f0, pkp(w.x, w.y), acc[2*k+0]);
            acc[2*k+1] = f2fma(f0, pkp(w.z, w.w), acc[2*k+1]);
        }
        const float4* r1 = &sW1[(32 + 2*dp+1) * 8];
        #pragma unroll
        for (int k = 0; k < 8; k++) {
            float4 w = r1[k];
            acc[2*k+0] = f2fma(f1, pkp(w.x, w.y), acc[2*k+0]);
            acc[2*k+1] = f2fma(f1, pkp(w.z, w.w), acc[2*k+1]);
        }
    }
    // rows 64..79: h_to @ We1[32:48]
    #pragma unroll
    for (int d = 0; d < 16; d++) {
        ULL fd = pk2(ft[d]);
        const float4* r = &sW1[(64 + d) * 8];
        #pragma unroll
        for (int k = 0; k < 8; k++) {
            float4 w = r[k];
            acc[2*k+0] = f2fma(fd, pkp(w.x, w.y), acc[2*k+0]);
            acc[2*k+1] = f2fma(fd, pkp(w.z, w.w), acc[2*k+1]);
        }
    }

    float hid[32];
    #pragma unroll
    for (int q = 0; q < 16; q++) {
        float2 p = up2(acc[q]);
        hid[2*q+0] = fmaxf(p.x, 0.f);
        hid[2*q+1] = fmaxf(p.y, 0.f);
    }

    ULL o[8];
    #pragma unroll
    for (int q = 0; q < 8; q++) o[q] = 0ull;
    #pragma unroll
    for (int j = 0; j < 32; j++) {
        ULL hj = pk2(hid[j]);
        #pragma unroll
        for (int k = 0; k < 4; k++) {
            float4 w = sW2[j*4 + k];
            o[2*k+0] = f2fma(hj, pkp(w.x, w.y), o[2*k+0]);
            o[2*k+1] = f2fma(hj, pkp(w.z, w.w), o[2*k+1]);
        }
    }

    float4* op = reinterpret_cast<float4*>(out + (size_t)idx * D_EMB);
    #pragma unroll
    for (int q = 0; q < 4; q++) op[q] = mk4(o[2*q], o[2*q+1]);
}

// ---------------------------------------------------------------------------
extern "C" void kernel_launch(void* const* d_in, const int* in_sizes, int n_in,
                              void* d_out, int out_size) {
    const float* h_from_x   = (const float*)d_in[0];
    const float* h_from_z   = (const float*)d_in[1];
    const float* h_to       = (const float*)d_in[2];
    const int*   syndrome_x = (const int*)d_in[3];
    const int*   syndrome_z = (const int*)d_in[4];
    const int*   from_ind_x = (const int*)d_in[5];
    const int*   to_ind_x   = (const int*)d_in[6];
    const int*   from_ind_z = (const int*)d_in[7];
    const int*   to_ind_z   = (const int*)d_in[8];
    const float* Wx1        = (const float*)d_in[9];
    const float* Wx2        = (const float*)d_in[10];
    const float* Wz1        = (const float*)d_in[11];
    const float* Wz2        = (const float*)d_in[12];
    const float* We1        = (const float*)d_in[13];
    const float* We2        = (const float*)d_in[14];
    float* out = (float*)d_out;

    __half *hf_x, *hf_z, *s;
    float *M;
    int *cnt, *offs_x, *offs_z;
    unsigned *csr_x, *csr_z, *mask_x, *mask_z;
    cudaGetSymbolAddress((void**)&hf_x, g_hf_x);
    cudaGetSymbolAddress((void**)&hf_z, g_hf_z);
    cudaGetSymbolAddress((void**)&s,    g_s);
    cudaGetSymbolAddress((void**)&M,    g_M);
    cudaGetSymbolAddress((void**)&cnt,  g_cnt);
    cudaGetSymbolAddress((void**)&offs_x, g_offs_x);
    cudaGetSymbolAddress((void**)&offs_z, g_offs_z);
    cudaGetSymbolAddress((void**)&csr_x, g_csr_x);
    cudaGetSymbolAddress((void**)&csr_z, g_csr_z);
    cudaGetSymbolAddress((void**)&mask_x, g_mask_x);
    cudaGetSymbolAddress((void**)&mask_z, g_mask_z);

    int *deg_x = cnt, *deg_z = cnt + NUM_VN;
    int *cur_x = cnt + 2 * NUM_VN, *cur_z = cnt + 3 * NUM_VN;

    cudaMemsetAsync(cnt, 0, 4 * NUM_VN * sizeof(int), 0);

    // k1: histogram + masks
    prep_kernel<<<(NUM_E + 255) / 256, 256>>>(
        to_ind_x, to_ind_z, syndrome_x, syndrome_z,
        deg_x, deg_z, mask_x, mask_z);

    // k2: scan (blocks 0,1) + combined-matrix precompute (block 2)
    scan_kernel<<<3, 1024>>>(deg_x, deg_z, offs_x, offs_z, Wx2, Wz2, We1, M);

    // k3: fused CSR fill (y=2) + node partials (y=0,1)
    fill_np_kernel<<<dim3(12500, 3), 256>>>(
        from_ind_x, to_ind_x, from_ind_z, to_ind_z,
        offs_x, offs_z, mask_x, mask_z, cur_x, cur_z, csr_x, csr_z,
        h_from_x, h_from_z, Wx1, Wz1, hf_x, hf_z);

    // k4 (profiled slot): messages — raw relu-sum, no projection
    msg_kernel<<<dim3(6250, 2), 256>>>(
        h_to, hf_x, hf_z,
        offs_x, csr_x, offs_z, csr_z,
        Wx1, Wz1, s);

    // k5: vertex MLP with folded W2
    vn_kernel<<<(NUM_VN * B_SZ) / 256, 256>>>(s, h_to, M, We1, We2, out);
}

// round 10
// speedup vs baseline: 1.2230x; 1.0839x over previous
#include <cuda_runtime.h>
#include <cuda_fp16.h>

#define B_SZ   16
#define NUM_CN 25000
#define NUM_VN 50000
#define NUM_E  200000
#define D_EMB  16
#define D_HID  32
#define D_MSG  16

typedef unsigned long long ULL;

// ---- scratch (device globals) ----
__device__ __half g_hf_x[(size_t)NUM_CN * B_SZ * D_HID];   // [CN][B][32] fp16
__device__ __half g_hf_z[(size_t)NUM_CN * B_SZ * D_HID];
__device__ __half g_s[(size_t)2 * B_SZ * NUM_VN * D_HID];  // [pol][b][VN][32] fp16
__device__ float  g_M[2 * 32 * 32];                        // Mx | Mz combined mats
__device__ int      g_cnt[4 * NUM_VN];                     // deg_x|deg_z|cur_x|cur_z
__device__ int      g_offs_x[NUM_VN + 1], g_offs_z[NUM_VN + 1];
__device__ unsigned g_csr_x[NUM_E],   g_csr_z[NUM_E];      // f | (mask<<16)
__device__ unsigned g_mask_x[NUM_CN], g_mask_z[NUM_CN];

// ---------------------------------------------------------------------------
// f32x2 packed helpers
__device__ __forceinline__ ULL pk2(float x) {
    ULL d; asm("mov.b64 %0, {%1, %1};" : "=l"(d) : "f"(x)); return d;
}
__device__ __forceinline__ ULL pkp(float x, float y) {
    ULL d; asm("mov.b64 %0, {%1, %2};" : "=l"(d) : "f"(x), "f"(y)); return d;
}
__device__ __forceinline__ float2 up2(ULL a) {
    float lo, hi; asm("mov.b64 {%0, %1}, %2;" : "=f"(lo), "=f"(hi) : "l"(a));
    return make_float2(lo, hi);
}
__device__ __forceinline__ ULL f2fma(ULL a, ULL b, ULL c) {
    ULL d; asm("fma.rn.f32x2 %0, %1, %2, %3;" : "=l"(d) : "l"(a), "l"(b), "l"(c));
    return d;
}
__device__ __forceinline__ float4 mk4(ULL a, ULL b) {
    float2 p = up2(a), q = up2(b);
    return make_float4(p.x, p.y, q.x, q.y);
}

// ---------------------------------------------------------------------------
// kernel 1: degree histogram + syndrome bitmask pack
__global__ void __launch_bounds__(256) prep_kernel(
    const int* __restrict__ to_x, const int* __restrict__ to_z,
    const int* __restrict__ syn_x, const int* __restrict__ syn_z,
    int* __restrict__ deg_x, int* __restrict__ deg_z,
    unsigned* __restrict__ mask_x, unsigned* __restrict__ mask_z)
{
    int i = blockIdx.x * 256 + threadIdx.x;
    if (i < NUM_E) {
        atomicAdd(&deg_x[__ldg(to_x + i)], 1);
        atomicAdd(&deg_z[__ldg(to_z + i)], 1);
    }
    if (i < NUM_CN) {
        unsigned mx = 0, mz = 0;
        #pragma unroll
        for (int b = 0; b < B_SZ; b++) {
            mx |= (unsigned)(__ldg(syn_x + (size_t)b * NUM_CN + i) & 1) << b;
            mz |= (unsigned)(__ldg(syn_z + (size_t)b * NUM_CN + i) & 1) << b;
        }
        mask_x[i] = mx;
        mask_z[i] = mz;
    }
}

// ---------------------------------------------------------------------------
// kernel 2: exclusive scan (blocks 0,1) + combined-matrix precompute (block 2)
__global__ void __launch_bounds__(1024) scan_kernel(
    const int* __restrict__ deg_x, const int* __restrict__ deg_z,
    int* __restrict__ offs_x, int* __restrict__ offs_z,
    const float* __restrict__ Wx2, const float* __restrict__ Wz2,
    const float* __restrict__ We1, float* __restrict__ M)
{
    if (blockIdx.x == 2) {
        int t = threadIdx.x;
        #pragma unroll
        for (int r = 0; r < 2; r++) {
            int el = r * 1024 + t;            // 0..2047
            int pol = el >> 10;               // 0: Mx, 1: Mz
            int i = (el >> 5) & 31;           // row (s dim)
            int j = el & 31;                  // col (hid dim)
            const float* W2 = pol ? Wz2 : Wx2;
            const float* E1 = We1 + pol * 16 * 32;
            float sum = 0.f;
            #pragma unroll
            for (int k = 0; k < 16; k++)
                sum += W2[i * 16 + k] * E1[k * 32 + j];
            M[el] = sum;
        }
        return;
    }

    const int* deg  = blockIdx.x == 0 ? deg_x  : deg_z;
    int*       offs = blockIdx.x == 0 ? offs_x : offs_z;

    __shared__ int wt[32];
    __shared__ int sbase;
    int t = threadIdx.x;
    int lane = t & 31, w = t >> 5;
    if (t == 0) sbase = 0;
    __syncthreads();

    for (int c = 0; c < NUM_VN; c += 1024) {
        int gid = c + t;
        int x = (gid < NUM_VN) ? deg[gid] : 0;
        #pragma unroll
        for (int o = 1; o < 32; o <<= 1) {
            int y = __shfl_up_sync(0xffffffffu, x, o);
            if (lane >= o) x += y;
        }
        if (lane == 31) wt[w] = x;
        __syncthreads();
        if (w == 0) {
            int y = wt[lane];
            #pragma unroll
            for (int o = 1; o < 32; o <<= 1) {
                int z = __shfl_up_sync(0xffffffffu, y, o);
                if (lane >= o) y += z;
            }
            wt[lane] = y;
        }
        __syncthreads();
        int incl = x + (w > 0 ? wt[w - 1] : 0) + sbase;
        if (gid < NUM_VN) offs[gid + 1] = incl;
        __syncthreads();
        if (t == 1023) sbase = incl;
        __syncthreads();
    }
    if (t == 0) offs[0] = 0;
}

// ---------------------------------------------------------------------------
// kernel 3: fused CSR fill (y=2) + node partials (y=0,1)
__global__ void __launch_bounds__(256) fill_np_kernel(
    const int* __restrict__ from_x, const int* __restrict__ to_x,
    const int* __restrict__ from_z, const int* __restrict__ to_z,
    const int* __restrict__ offs_x, const int* __restrict__ offs_z,
    const unsigned* __restrict__ mask_x, const unsigned* __restrict__ mask_z,
    int* __restrict__ cur_x, int* __restrict__ cur_z,
    unsigned* __restrict__ csr_x, unsigned* __restrict__ csr_z,
    const float* __restrict__ hx, const float* __restrict__ hz,
    const float* __restrict__ Wx1, const float* __restrict__ Wz1,
    __half* __restrict__ ox, __half* __restrict__ oz)
{
    if (blockIdx.y == 2) {
        int e = blockIdx.x * 256 + threadIdx.x;
        if (e >= NUM_E) return;
        {
            int v = __ldg(to_x + e);
            int f = __ldg(from_x + e);
            int p = atomicAdd(&cur_x[v], 1);
            csr_x[__ldg(offs_x + v) + p] = (unsigned)f | (__ldg(mask_x + f) << 16);
        }
        {
            int v = __ldg(to_z + e);
            int f = __ldg(from_z + e);
            int p = atomicAdd(&cur_z[v], 1);
            csr_z[__ldg(offs_z + v) + p] = (unsigned)f | (__ldg(mask_z + f) << 16);
        }
        return;
    }

    const float* h  = blockIdx.y == 0 ? hx  : hz;
    const float* W1 = blockIdx.y == 0 ? Wx1 : Wz1;
    __half*      o  = blockIdx.y == 0 ? ox  : oz;

    __shared__ float4 sW1[128];   // W1 rows 0..15 (16x32)
    int t = threadIdx.x;
    if (t < 128) sW1[t] = reinterpret_cast<const float4*>(W1)[t];
    __syncthreads();

    int wid = t >> 5;
    int unit = blockIdx.x * 8 + wid;          // n*4 + bgroup, < 100000
    if (unit >= NUM_CN * 4) return;
    int n = unit >> 2;
    int b = ((unit & 3) << 2) | ((t >> 3) & 3);
    int chunk = t & 7;

    const float4* ph = reinterpret_cast<const float4*>(h + ((size_t)b * NUM_CN + n) * D_EMB);
    float4 h0 = ph[0], h1 = ph[1], h2 = ph[2], h3 = ph[3];
    float hr[16] = {h0.x,h0.y,h0.z,h0.w, h1.x,h1.y,h1.z,h1.w,
                    h2.x,h2.y,h2.z,h2.w, h3.x,h3.y,h3.z,h3.w};

    ULL a0 = 0ull, a1 = 0ull;
    #pragma unroll
    for (int d = 0; d < 16; d++) {
        float4 w = sW1[d*8 + chunk];
        ULL hd = pk2(hr[d]);
        a0 = f2fma(hd, pkp(w.x, w.y), a0);
        a1 = f2fma(hd, pkp(w.z, w.w), a1);
    }

    __half2 lo = __float22half2_rn(up2(a0));
    __half2 hi = __float22half2_rn(up2(a1));
    uint2 st;
    st.x = *reinterpret_cast<unsigned*>(&lo);
    st.y = *reinterpret_cast<unsigned*>(&hi);
    reinterpret_cast<uint2*>(o)[((size_t)n * B_SZ + b) * 8 + chunk] = st;
}

// ---------------------------------------------------------------------------
// kernel 4 (PROFILED SLOT): msg kernel — inverted loop nest.
// warp = one v; lane = b_hi*8 + chunk; lane covers b = {0,1,2,3}*4 + b_hi.
// Per edge: ONE uniform csr load, ONE 32-bit base IMAD, FOUR independent
// predicated gathers (one per b-group). hp hoisted for all 4 b.
__global__ void __launch_bounds__(256) msg_kernel(
    const float* __restrict__ h_to,
    const __half* __restrict__ hfx, const __half* __restrict__ hfz,
    const int* __restrict__ offs_x, const unsigned* __restrict__ csr_x,
    const int* __restrict__ offs_z, const unsigned* __restrict__ csr_z,
    const float* __restrict__ Wx1, const float* __restrict__ Wz1,
    __half* __restrict__ s_out)
{
    int pol = blockIdx.y;
    const uint2*    hf2  = reinterpret_cast<const uint2*>(pol ? hfz : hfx);
    const int*      offs = pol ? offs_z : offs_x;
    const unsigned* csr  = pol ? csr_z  : csr_x;

    __shared__ float4 sW1[128];   // W1 rows 16..31 (16x32)
    {
        const float4* w1 = reinterpret_cast<const float4*>((pol ? Wz1 : Wx1) + 16 * 32);
        int t = threadIdx.x;
        if (t < 128) sW1[t] = w1[t];
    }
    __syncthreads();

    int t = threadIdx.x;
    int wid = t >> 5;
    int lane = t & 31;
    int v = blockIdx.x * 8 + wid;             // grid.x=6250 -> v in [0,50000)
    int b_hi = (lane >> 3) & 3;
    int chunk = lane & 7;

    // hoist hp for all 4 b-groups: hp[bg] = h_to[bg*4+b_hi][v] @ W1[16:32] (4 dims)
    float2 hpa[4], hpb[4];
    #pragma unroll
    for (int bg = 0; bg < 4; bg++) {
        int b = bg * 4 + b_hi;
        const float4* ph = reinterpret_cast<const float4*>(
            h_to + ((size_t)b * NUM_VN + v) * D_EMB);
        float4 h0 = ph[0], h1 = ph[1], h2 = ph[2], h3 = ph[3];
        float hr[16] = {h0.x,h0.y,h0.z,h0.w, h1.x,h1.y,h1.z,h1.w,
                        h2.x,h2.y,h2.z,h2.w, h3.x,h3.y,h3.z,h3.w};
        ULL a0 = 0ull, a1 = 0ull;
        #pragma unroll
        for (int d = 0; d < 16; d++) {
            float4 w = sW1[d*8 + chunk];
            ULL hd = pk2(hr[d]);
            a0 = f2fma(hd, pkp(w.x, w.y), a0);
            a1 = f2fma(hd, pkp(w.z, w.w), a1);
        }
        hpa[bg] = up2(a0);
        hpb[bg] = up2(a1);
    }

    float s0[4] = {0,0,0,0}, s1[4] = {0,0,0,0};
    float s2[4] = {0,0,0,0}, s3[4] = {0,0,0,0};

    int beg = __ldg(offs + v), end = __ldg(offs + v + 1);
    unsigned shift0 = 16 + b_hi;
    unsigned lane_off = (unsigned)(b_hi * 8 + chunk);   // uint2 offset for bg=0

    // 2-wide edge unroll; per edge 4 independent gathers (one per bg)
    for (int e = beg; e < end; e += 2) {
        unsigned pka = __ldg(csr + e);
        unsigned pkb = (e + 1 < end) ? __ldg(csr + e + 1) : 0u;

        unsigned basea = (pka & 0xFFFFu) * 128u + lane_off;
        unsigned baseb = (pkb & 0xFFFFu) * 128u + lane_off;

        uint2 va[4], vb[4];
        bool ga[4], gb[4];
        #pragma unroll
        for (int bg = 0; bg < 4; bg++) {
            ga[bg] = (pka >> (shift0 + bg * 4)) & 1u;
            gb[bg] = (pkb >> (shift0 + bg * 4)) & 1u;
            if (ga[bg]) va[bg] = __ldg(hf2 + basea + bg * 32u);
            if (gb[bg]) vb[bg] = __ldg(hf2 + baseb + bg * 32u);
        }
        #pragma unroll
        for (int bg = 0; bg < 4; bg++) {
            if (ga[bg]) {
                float2 lo = __half22float2(*reinterpret_cast<__half2*>(&va[bg].x));
                float2 hi = __half22float2(*reinterpret_cast<__half2*>(&va[bg].y));
                s0[bg] += fmaxf(lo.x + hpa[bg].x, 0.f);
                s1[bg] += fmaxf(lo.y + hpa[bg].y, 0.f);
                s2[bg] += fmaxf(hi.x + hpb[bg].x, 0.f);
                s3[bg] += fmaxf(hi.y + hpb[bg].y, 0.f);
            }
            if (gb[bg]) {
                float2 lo = __half22float2(*reinterpret_cast<__half2*>(&vb[bg].x));
                float2 hi = __half22float2(*reinterpret_cast<__half2*>(&vb[bg].y));
                s0[bg] += fmaxf(lo.x + hpa[bg].x, 0.f);
                s1[bg] += fmaxf(lo.y + hpa[bg].y, 0.f);
                s2[bg] += fmaxf(hi.x + hpb[bg].x, 0.f);
                s3[bg] += fmaxf(hi.y + hpb[bg].y, 0.f);
            }
        }
    }

    // store raw s per bg, layout [pol][b][VN][32]
    #pragma unroll
    for (int bg = 0; bg < 4; bg++) {
        int b = bg * 4 + b_hi;
        __half2 lo = __float22half2_rn(make_float2(s0[bg], s1[bg]));
        __half2 hi = __float22half2_rn(make_float2(s2[bg], s3[bg]));
        uint2 st;
        st.x = *reinterpret_cast<unsigned*>(&lo);
        st.y = *reinterpret_cast<unsigned*>(&hi);
        reinterpret_cast<uint2*>(s_out)[
            (((size_t)pol * B_SZ + b) * NUM_VN + v) * 8 + chunk] = st;
    }
}

// ---------------------------------------------------------------------------
// kernel 5: vn kernel — out = relu(sx@Mx + sz@Mz + h_to@We1[32:48]) @ We2
__global__ void __launch_bounds__(256) vn_kernel(
    const __half* __restrict__ s, const float* __restrict__ h_to,
    const float* __restrict__ M, const float* __restrict__ We1,
    const float* __restrict__ We2, float* __restrict__ out)
{
    __shared__ float4 sW1[640];   // 80 rows x 32 cols: Mx(32) | Mz(32) | We1[32:48](16)
    __shared__ float4 sW2[128];   // We2 32x16
    int t = threadIdx.x;
    for (int i = t; i < 512; i += 256) sW1[i] = reinterpret_cast<const float4*>(M)[i];
    if (t < 128) sW1[512 + t] = reinterpret_cast<const float4*>(We1 + 32 * 32)[t];
    if (t < 128) sW2[t] = reinterpret_cast<const float4*>(We2)[t];
    __syncthreads();

    int idx = blockIdx.x * 256 + t;   // idx = b*NUM_VN + v  (800000 = 3125*256)
    const size_t BVN = (size_t)B_SZ * NUM_VN;

    unsigned ux[16], uz[16];
    {
        const uint4* px = reinterpret_cast<const uint4*>(s) + (size_t)idx * 4;
        const uint4* pz = reinterpret_cast<const uint4*>(s) + (BVN + idx) * 4;
        #pragma unroll
        for (int q = 0; q < 4; q++) {
            uint4 a = px[q];
            ux[4*q+0]=a.x; ux[4*q+1]=a.y; ux[4*q+2]=a.z; ux[4*q+3]=a.w;
        }
        #pragma unroll
        for (int q = 0; q < 4; q++) {
            uint4 a = pz[q];
            uz[4*q+0]=a.x; uz[4*q+1]=a.y; uz[4*q+2]=a.z; uz[4*q+3]=a.w;
        }
    }
    float ft[16];
    {
        const float4* ph = reinterpret_cast<const float4*>(h_to + (size_t)idx * D_EMB);
        #pragma unroll
        for (int q = 0; q < 4; q++) {
            float4 a = ph[q];
            ft[4*q+0]=a.x; ft[4*q+1]=a.y; ft[4*q+2]=a.z; ft[4*q+3]=a.w;
        }
    }

    ULL acc[16];
    #pragma unroll
    for (int q = 0; q < 16; q++) acc[q] = 0ull;

    #pragma unroll
    for (int dp = 0; dp < 16; dp++) {
        float2 p = __half22float2(*reinterpret_cast<__half2*>(&ux[dp]));
        ULL f0 = pk2(p.x), f1 = pk2(p.y);
        const float4* r0 = &sW1[(2*dp) * 8];
        #pragma unroll
        for (int k = 0; k < 8; k++) {
            float4 w = r0[k];
            acc[2*k+0] = f2fma(f0, pkp(w.x, w.y), acc[2*k+0]);
            acc[2*k+1] = f2fma(f0, pkp(w.z, w.w), acc[2*k+1]);
        }
        const float4* r1 = &sW1[(2*dp+1) * 8];
        #pragma unroll
        for (int k = 0; k < 8; k++) {
            float4 w = r1[k];
            acc[2*k+0] = f2fma(f1, pkp(w.x, w.y), acc[2*k+0]);
            acc[2*k+1] = f2fma(f1, pkp(w.z, w.w), acc[2*k+1]);
        }
    }
    #pragma unroll
    for (int dp = 0; dp < 16; dp++) {
        float2 p = __half22float2(*reinterpret_cast<__half2*>(&uz[dp]));
        ULL f0 = pk2(p.x), f1 = pk2(p.y);
        const float4* r0 = &sW1[(32 + 2*dp) * 8];
        #pragma unroll
        for (int k = 0; k < 8; k++) {
            float4 w = r0[k];
            acc[2*k+0] = f2fma(f0, pkp(w.x, w.y), acc[2*k+0]);
            acc[2*k+1] = f2fma(f0, pkp(w.z, w.w), acc[2*k+1]);
        }
        const float4* r1 = &sW1[(32 + 2*dp+1) * 8];
        #pragma unroll
        for (int k = 0; k < 8; k++) {
            float4 w = r1[k];
            acc[2*k+0] = f2fma(f1, pkp(w.x, w.y), acc[2*k+0]);
            acc[2*k+1] = f2fma(f1, pkp(w.z, w.w), acc[2*k+1]);
        }
    }
    #pragma unroll
    for (int d = 0; d < 16; d++) {
        ULL fd = pk2(ft[d]);
        const float4* r = &sW1[(64 + d) * 8];
        #pragma unroll
        for (int k = 0; k < 8; k++) {
            float4 w = r[k];
            acc[2*k+0] = f2fma(fd, pkp(w.x, w.y), acc[2*k+0]);
            acc[2*k+1] = f2fma(fd, pkp(w.z, w.w), acc[2*k+1]);
        }
    }

    float hid[32];
    #pragma unroll
    for (int q = 0; q < 16; q++) {
        float2 p = up2(acc[q]);
        hid[2*q+0] = fmaxf(p.x, 0.f);
        hid[2*q+1] = fmaxf(p.y, 0.f);
    }

    ULL o[8];
    #pragma unroll
    for (int q = 0; q < 8; q++) o[q] = 0ull;
    #pragma unroll
    for (int j = 0; j < 32; j++) {
        ULL hj = pk2(hid[j]);
        #pragma unroll
        for (int k = 0; k < 4; k++) {
            float4 w = sW2[j*4 + k];
            o[2*k+0] = f2fma(hj, pkp(w.x, w.y), o[2*k+0]);
            o[2*k+1] = f2fma(hj, pkp(w.z, w.w), o[2*k+1]);
        }
    }

    float4* op = reinterpret_cast<float4*>(out + (size_t)idx * D_EMB);
    #pragma unroll
    for (int q = 0; q < 4; q++) op[q] = mk4(o[2*q], o[2*q+1]);
}

// ---------------------------------------------------------------------------
extern "C" void kernel_launch(void* const* d_in, const int* in_sizes, int n_in,
                              void* d_out, int out_size) {
    const float* h_from_x   = (const float*)d_in[0];
    const float* h_from_z   = (const float*)d_in[1];
    const float* h_to       = (const float*)d_in[2];
    const int*   syndrome_x = (const int*)d_in[3];
    const int*   syndrome_z = (const int*)d_in[4];
    const int*   from_ind_x = (const int*)d_in[5];
    const int*   to_ind_x   = (const int*)d_in[6];
    const int*   from_ind_z = (const int*)d_in[7];
    const int*   to_ind_z   = (const int*)d_in[8];
    const float* Wx1        = (const float*)d_in[9];
    const float* Wx2        = (const float*)d_in[10];
    const float* Wz1        = (const float*)d_in[11];
    const float* Wz2        = (const float*)d_in[12];
    const float* We1        = (const float*)d_in[13];
    const float* We2        = (const float*)d_in[14];
    float* out = (float*)d_out;

    __half *hf_x, *hf_z, *s;
    float *M;
    int *cnt, *offs_x, *offs_z;
    unsigned *csr_x, *csr_z, *mask_x, *mask_z;
    cudaGetSymbolAddress((void**)&hf_x, g_hf_x);
    cudaGetSymbolAddress((void**)&hf_z, g_hf_z);
    cudaGetSymbolAddress((void**)&s,    g_s);
    cudaGetSymbolAddress((void**)&M,    g_M);
    cudaGetSymbolAddress((void**)&cnt,  g_cnt);
    cudaGetSymbolAddress((void**)&offs_x, g_offs_x);
    cudaGetSymbolAddress((void**)&offs_z, g_offs_z);
    cudaGetSymbolAddress((void**)&csr_x, g_csr_x);
    cudaGetSymbolAddress((void**)&csr_z, g_csr_z);
    cudaGetSymbolAddress((void**)&mask_x, g_mask_x);
    cudaGetSymbolAddress((void**)&mask_z, g_mask_z);

    int *deg_x = cnt, *deg_z = cnt + NUM_VN;
    int *cur_x = cnt + 2 * NUM_VN, *cur_z = cnt + 3 * NUM_VN;

    cudaMemsetAsync(cnt, 0, 4 * NUM_VN * sizeof(int), 0);

    // k1: histogram + masks
    prep_kernel<<<(NUM_E + 255) / 256, 256>>>(
        to_ind_x, to_ind_z, syndrome_x, syndrome_z,
        deg_x, deg_z, mask_x, mask_z);

    // k2: scan (blocks 0,1) + combined-matrix precompute (block 2)
    scan_kernel<<<3, 1024>>>(deg_x, deg_z, offs_x, offs_z, Wx2, Wz2, We1, M);

    // k3: fused CSR fill (y=2) + node partials (y=0,1)
    fill_np_kernel<<<dim3(12500, 3), 256>>>(
        from_ind_x, to_ind_x, from_ind_z, to_ind_z,
        offs_x, offs_z, mask_x, mask_z, cur_x, cur_z, csr_x, csr_z,
        h_from_x, h_from_z, Wx1, Wz1, hf_x, hf_z);

    // k4 (profiled slot): messages — inverted loop nest
    msg_kernel<<<dim3(6250, 2), 256>>>(
        h_to, hf_x, hf_z,
        offs_x, csr_x, offs_z, csr_z,
        Wx1, Wz1, s);

    // k5: vertex MLP with folded W2
    vn_kernel<<<(NUM_VN * B_SZ) / 256, 256>>>(s, h_to, M, We1, We2, out);
}